// round 15
// baseline (speedup 1.0000x reference)
#include <cuda_runtime.h>
#include <cuda_fp16.h>
#include <math.h>

#define NMAX 50000
#define EMAX 600000
#define F    128
#define NCLSK 40
#define BN_EPS 1e-5f

typedef unsigned long long u64;
typedef unsigned int uint32;

// ---------------- scratch (device globals; no allocation allowed) ----------------
__device__ uint2  g_aggh  [NMAX * 32];  // fp16 aggregation output (GEMM A input)
__device__ uint2  g_hlin0 [NMAX * 32];  // layer-0 GEMM output (fp16, pre-BN)
__device__ uint2  g_hlin1 [NMAX * 32];  // layer-1 GEMM output (fp16, pre-BN)
__device__ uint2  g_feath [NMAX * 32];  // fp16 feature rows (gather source)
__device__ __half g_wt0   [F * 136];    // W0 fp16, n-major padded [n][k:136]
__device__ __half g_wt1   [F * 136];    // W1 fp16, n-major padded
__device__ int    g_deg [NMAX];
__device__ int    g_off [NMAX];
__device__ int    g_cur [NMAX];
__device__ int    g_csrc[EMAX];         // stores src*32 (uint2 row base index)
__device__ float  g_invdeg[NMAX];
__device__ float  g_stats[4 * F];   // layer0: [0..255], layer1: [256..511]
__device__ int    g_counter;

// ------ combined: fp32->fp16 convert of x  +  degree histogram ------
__global__ __launch_bounds__(256) void conv_hist_kernel(const float4* __restrict__ x,
                                                        int total4,
                                                        const int* __restrict__ ei,
                                                        int ne, int n, int convB) {
    int tid = threadIdx.x;
    if (blockIdx.x == 0) {
        g_stats[tid] = 0.f;
        g_stats[256 + tid] = 0.f;
        if (tid == 0) g_counter = 0;
    }
    if (blockIdx.x < convB) {
        int i = blockIdx.x * 256 + tid;
        if (i < total4) {
            float4 v = __ldg(&x[i]);
            __half2 h01 = __floats2half2_rn(v.x, v.y);
            __half2 h23 = __floats2half2_rn(v.z, v.w);
            uint2 r;
            r.x = *(uint32*)&h01;
            r.y = *(uint32*)&h23;
            g_feath[i] = r;
        }
    } else {
        int i = (blockIdx.x - convB) * 256 + tid;
        int base = i * 4;
        const int* dst = ei + ne;
        bool vec_ok = ((ne & 3) == 0) && (base + 3 < ne);
        if (vec_ok) {
            int4 d = __ldg((const int4*)(dst + base));
            if ((unsigned)d.x < (unsigned)n) atomicAdd(&g_deg[d.x], 1);
            if ((unsigned)d.y < (unsigned)n) atomicAdd(&g_deg[d.y], 1);
            if ((unsigned)d.z < (unsigned)n) atomicAdd(&g_deg[d.z], 1);
            if ((unsigned)d.w < (unsigned)n) atomicAdd(&g_deg[d.w], 1);
        } else {
            for (int e = base; e < ne && e < base + 4; e++) {
                int d = dst[e];
                if ((unsigned)d < (unsigned)n) atomicAdd(&g_deg[d], 1);
            }
        }
    }
}

// ------- one-shot: convert W0/W1 fp32 [k][n] -> fp16 n-major padded ---------
__global__ __launch_bounds__(256) void wconv_kernel(const float* __restrict__ W0,
                                                    const float* __restrict__ W1) {
    int idx = blockIdx.x * 256 + threadIdx.x;    // 2 * 128 * 136 = 34816 total
    if (idx >= 2 * F * 136) return;
    int sel = idx >= F * 136;
    int j = idx - sel * (F * 136);
    int nrow = j / 136;
    int k = j - nrow * 136;
    const float* W = sel ? W1 : W0;
    __half* dst = sel ? g_wt1 : g_wt0;
    dst[nrow * 136 + k] = (k < F) ? __float2half(__ldg(&W[k * F + nrow]))
                                  : __half(0.f);
}

// -- node-wise BN+ReLU on fp16 h -> fp16 features for the next gather --------
__global__ __launch_bounds__(256) void bnrelu_h_kernel(const uint2* __restrict__ h,
                                                       const float* __restrict__ stats,
                                                       const float* __restrict__ g,
                                                       const float* __restrict__ be,
                                                       int n, int total4) {
    __shared__ float s_sc[F], s_sh[F];
    int tid = threadIdx.x;
    if (tid < F) {
        float mean = stats[tid] / (float)n;
        float var  = stats[F + tid] / (float)n - mean * mean;
        float sck = g[tid] * rsqrtf(var + BN_EPS);
        s_sc[tid] = sck;
        s_sh[tid] = be[tid] - mean * sck;
    }
    __syncthreads();
    int i = blockIdx.x * 256 + tid;
    if (i < total4) {
        int c4 = (i & 31) * 4;
        uint2 hv = __ldg(&h[i]);
        float2 f01 = __half22float2(*(__half2*)&hv.x);
        float2 f23 = __half22float2(*(__half2*)&hv.y);
        float4 sc = *(const float4*)&s_sc[c4];
        float4 sh = *(const float4*)&s_sh[c4];
        float vx = fmaxf(f01.x * sc.x + sh.x, 0.f);
        float vy = fmaxf(f01.y * sc.y + sh.y, 0.f);
        float vz = fmaxf(f23.x * sc.z + sh.z, 0.f);
        float vw = fmaxf(f23.y * sc.w + sh.w, 0.f);
        __half2 h01 = __floats2half2_rn(vx, vy);
        __half2 h23 = __floats2half2_rn(vz, vw);
        uint2 r;
        r.x = *(uint32*)&h01;
        r.y = *(uint32*)&h23;
        g_feath[i] = r;
    }
}

// ---------------- one-pass block scan with atomic base ----------------
__global__ __launch_bounds__(256) void scan_blocks_kernel(int n) {
    int tid = threadIdx.x;
    int i = blockIdx.x * 256 + tid;
    int v = (i < n) ? g_deg[i] : 0;

    int incl = v;
    #pragma unroll
    for (int o = 1; o < 32; o <<= 1) {
        int t = __shfl_up_sync(0xffffffffu, incl, o);
        if ((tid & 31) >= o) incl += t;
    }
    __shared__ int wsum[8];
    if ((tid & 31) == 31) wsum[tid >> 5] = incl;
    __syncthreads();
    if (tid < 8) {
        int w = wsum[tid];
        int s = w;
        #pragma unroll
        for (int o = 1; o < 8; o <<= 1) {
            int t = __shfl_up_sync(0x000000ffu, s, o);
            if (tid >= o) s += t;
        }
        wsum[tid] = s - w;
    }
    __syncthreads();
    incl += wsum[tid >> 5];

    __shared__ int base_s;
    if (tid == 255) base_s = atomicAdd(&g_counter, incl);
    __syncthreads();

    if (i < n) {
        int off = base_s + incl - v;
        g_off[i] = off;
        g_cur[i] = off;
        g_invdeg[i] = 1.0f / fmaxf((float)v, 1.0f);
    }
}

// ---------- CSR fill, 4 edges/thread; stores src*32 (uint2 row base) --------
__global__ __launch_bounds__(256) void fill_kernel(const int* __restrict__ ei,
                                                   int ne, int n) {
    int i = blockIdx.x * 256 + threadIdx.x;
    int base = i * 4;
    const int* src = ei;
    const int* dst = ei + ne;
    bool vec_ok = ((ne & 3) == 0) && (base + 3 < ne);
    if (vec_ok) {
        int4 s = __ldg((const int4*)(src + base));
        int4 d = __ldg((const int4*)(dst + base));
        if ((unsigned)d.x < (unsigned)n && (unsigned)s.x < (unsigned)n)
            g_csrc[atomicAdd(&g_cur[d.x], 1)] = s.x * 32;
        if ((unsigned)d.y < (unsigned)n && (unsigned)s.y < (unsigned)n)
            g_csrc[atomicAdd(&g_cur[d.y], 1)] = s.y * 32;
        if ((unsigned)d.z < (unsigned)n && (unsigned)s.z < (unsigned)n)
            g_csrc[atomicAdd(&g_cur[d.z], 1)] = s.z * 32;
        if ((unsigned)d.w < (unsigned)n && (unsigned)s.w < (unsigned)n)
            g_csrc[atomicAdd(&g_cur[d.w], 1)] = s.w * 32;
    } else {
        for (int e = base; e < ne && e < base + 4; e++) {
            int d = dst[e], s = src[e];
            if ((unsigned)d < (unsigned)n && (unsigned)s < (unsigned)n)
                g_csrc[atomicAdd(&g_cur[d], 1)] = s * 32;
        }
    }
}

// -- mean aggregation over fp16 rows, pairwise HADD2; emits fp16 (uint2/lane) --
__global__ __launch_bounds__(256) void agg_h_kernel(uint2* __restrict__ outh, int n) {
    int wid  = threadIdx.x >> 5;
    int lane = threadIdx.x & 31;
    int node = blockIdx.x * 8 + wid;
    if (node >= n) return;
    int beg = g_off[node];
    int deg = g_deg[node];
    int end = beg + deg;
    float4 acc  = make_float4(0.f, 0.f, 0.f, 0.f);
    float4 acc2 = make_float4(0.f, 0.f, 0.f, 0.f);
    int e = beg;
    int m4 = beg + (deg & ~3);
    for (; e < m4; e += 4) {
        int i0 = g_csrc[e],   i1 = g_csrc[e+1];
        int i2 = g_csrc[e+2], i3 = g_csrc[e+3];
        uint2 r0 = __ldg(&g_feath[i0 + lane]);
        uint2 r1 = __ldg(&g_feath[i1 + lane]);
        uint2 r2 = __ldg(&g_feath[i2 + lane]);
        uint2 r3 = __ldg(&g_feath[i3 + lane]);
        __half2 s0x = __hadd2(*(__half2*)&r0.x, *(__half2*)&r1.x);
        __half2 s0y = __hadd2(*(__half2*)&r0.y, *(__half2*)&r1.y);
        __half2 s1x = __hadd2(*(__half2*)&r2.x, *(__half2*)&r3.x);
        __half2 s1y = __hadd2(*(__half2*)&r2.y, *(__half2*)&r3.y);
        float2 f0x = __half22float2(s0x);
        float2 f0y = __half22float2(s0y);
        float2 f1x = __half22float2(s1x);
        float2 f1y = __half22float2(s1y);
        acc.x  += f0x.x; acc.y  += f0x.y; acc.z  += f0y.x; acc.w  += f0y.y;
        acc2.x += f1x.x; acc2.y += f1x.y; acc2.z += f1y.x; acc2.w += f1y.y;
    }
    if (e + 1 < end) {
        int i0 = g_csrc[e], i1 = g_csrc[e+1];
        uint2 r0 = __ldg(&g_feath[i0 + lane]);
        uint2 r1 = __ldg(&g_feath[i1 + lane]);
        __half2 sx = __hadd2(*(__half2*)&r0.x, *(__half2*)&r1.x);
        __half2 sy = __hadd2(*(__half2*)&r0.y, *(__half2*)&r1.y);
        float2 fx = __half22float2(sx);
        float2 fy = __half22float2(sy);
        acc.x += fx.x; acc.y += fx.y; acc.z += fy.x; acc.w += fy.y;
        e += 2;
    }
    if (e < end) {
        int i0 = g_csrc[e];
        uint2 r0 = __ldg(&g_feath[i0 + lane]);
        float2 p0 = __half22float2(*(__half2*)&r0.x);
        float2 p1 = __half22float2(*(__half2*)&r0.y);
        acc.x += p0.x; acc.y += p0.y; acc.z += p1.x; acc.w += p1.y;
    }
    float inv = g_invdeg[node];
    __half2 o01 = __floats2half2_rn((acc.x + acc2.x) * inv, (acc.y + acc2.y) * inv);
    __half2 o23 = __floats2half2_rn((acc.z + acc2.z) * inv, (acc.w + acc2.w) * inv);
    uint2 o;
    o.x = *(uint32*)&o01;
    o.y = *(uint32*)&o23;
    outh[node * 32 + lane] = o;
}

// -- fp16 HMMA GEMM v2: pre-converted fp16 W, fp16 A in, fp16 C out + stats --
// smem: As[128][136] half + Wt[128][136] half + 2*128 float = 70656 B dynamic
#define GEMM_SMEM_BYTES (34816 * 2 + 1024)
__device__ __forceinline__ void mma_f16(float d[4], uint32 a0, uint32 a1,
                                        uint32 a2, uint32 a3,
                                        uint32 b0, uint32 b1) {
    asm("mma.sync.aligned.m16n8k16.row.col.f32.f16.f16.f32 "
        "{%0,%1,%2,%3}, {%4,%5,%6,%7}, {%8,%9}, {%0,%1,%2,%3};"
        : "+f"(d[0]), "+f"(d[1]), "+f"(d[2]), "+f"(d[3])
        : "r"(a0), "r"(a1), "r"(a2), "r"(a3), "r"(b0), "r"(b1));
}

__global__ __launch_bounds__(256, 2) void gemm_hmma_stats_kernel(
        const uint4* __restrict__ Ah,     // fp16 A rows: 16 uint4 per row
        const uint4* __restrict__ Wt_g,   // fp16 W n-major [128][136] = [128][17] uint4
        const float* __restrict__ bias,
        uint32* __restrict__ C,           // fp16 C rows: 64 uint32 per row
        float* __restrict__ stats, int n) {
    extern __shared__ char smraw[];
    __half* As = (__half*)smraw;                 // [128][136]
    __half* Wt = (__half*)(smraw + 34816);       // [128][136], n-major
    float*  s_sum = (float*)(smraw + 69632);
    float*  s_sq  = s_sum + F;

    int tid = threadIdx.x;
    int block_row = blockIdx.x * 128;

    // ---- stage A tile (fp16, already converted) ----
    {
        int row = tid >> 1;
        int cofs = (tid & 1) * 8;
        uint4* Asu4 = (uint4*)As;          // row stride 17 uint4 (136 halves)
        int grow = block_row + row;
        if (grow < n) {
            const uint4* src = Ah + (size_t)grow * 16 + cofs;
            #pragma unroll
            for (int i = 0; i < 8; i++)
                Asu4[row * 17 + cofs + i] = __ldg(&src[i]);
        } else {
            uint4 z = make_uint4(0, 0, 0, 0);
            #pragma unroll
            for (int i = 0; i < 8; i++)
                Asu4[row * 17 + cofs + i] = z;
        }
    }
    // ---- stage Wt: pure copy of pre-converted fp16 (no math) ----
    {
        uint4* Wtu4 = (uint4*)Wt;
        for (int idx = tid; idx < F * 17; idx += 256)
            Wtu4[idx] = __ldg(&Wt_g[idx]);
    }
    if (tid < F) { s_sum[tid] = 0.f; s_sq[tid] = 0.f; }
    __syncthreads();

    int wid = tid >> 5, lane = tid & 31;
    int wr = (wid & 3) * 32;     // warp row base
    int wc = (wid >> 2) * 64;    // warp col base
    int qr = lane >> 2;          // 0..7
    int qc = lane & 3;           // 0..3

    float d[2][8][4];
    #pragma unroll
    for (int mt = 0; mt < 2; mt++)
        #pragma unroll
        for (int nt = 0; nt < 8; nt++)
            #pragma unroll
            for (int k = 0; k < 4; k++) d[mt][nt][k] = 0.f;

    uint32 As_base = (uint32)__cvta_generic_to_shared(As);
    int a_row_in = lane & 15;
    int a_kofs = (lane >> 4) * 8;

    #pragma unroll
    for (int ks = 0; ks < 8; ks++) {
        uint32 a[2][4];
        #pragma unroll
        for (int mt = 0; mt < 2; mt++) {
            uint32 addr = As_base +
                (((wr + mt * 16 + a_row_in) * 136) + ks * 16 + a_kofs) * 2;
            asm volatile(
                "ldmatrix.sync.aligned.m8n8.x4.shared.b16 {%0,%1,%2,%3}, [%4];"
                : "=r"(a[mt][0]), "=r"(a[mt][1]), "=r"(a[mt][2]), "=r"(a[mt][3])
                : "r"(addr));
        }
        int k0 = ks * 16 + qc * 2;
        #pragma unroll
        for (int nt = 0; nt < 8; nt++) {
            int nidx = wc + nt * 8 + qr;
            uint32 b0 = *(const uint32*)&Wt[nidx * 136 + k0];
            uint32 b1 = *(const uint32*)&Wt[nidx * 136 + k0 + 8];
            mma_f16(d[0][nt], a[0][0], a[0][1], a[0][2], a[0][3], b0, b1);
            mma_f16(d[1][nt], a[1][0], a[1][1], a[1][2], a[1][3], b0, b1);
        }
    }

    // ---- epilogue: bias + fp16 C write + BN stats ----
    #pragma unroll
    for (int nt = 0; nt < 8; nt++) {
        int col = wc + nt * 8 + qc * 2;     // even
        float b0v = __ldg(&bias[col]);
        float b1v = __ldg(&bias[col + 1]);
        float s0 = 0.f, q0 = 0.f, s1 = 0.f, q1 = 0.f;
        #pragma unroll
        for (int mt = 0; mt < 2; mt++) {
            int r0 = block_row + wr + mt * 16 + qr;
            int r1 = r0 + 8;
            float v00 = d[mt][nt][0] + b0v;
            float v01 = d[mt][nt][1] + b1v;
            float v10 = d[mt][nt][2] + b0v;
            float v11 = d[mt][nt][3] + b1v;
            if (r0 < n) {
                __half2 hp = __floats2half2_rn(v00, v01);
                C[(size_t)r0 * 64 + (col >> 1)] = *(uint32*)&hp;
                s0 += v00; q0 += v00 * v00;
                s1 += v01; q1 += v01 * v01;
            }
            if (r1 < n) {
                __half2 hp = __floats2half2_rn(v10, v11);
                C[(size_t)r1 * 64 + (col >> 1)] = *(uint32*)&hp;
                s0 += v10; q0 += v10 * v10;
                s1 += v11; q1 += v11 * v11;
            }
        }
        atomicAdd(&s_sum[col], s0);
        atomicAdd(&s_sq[col], q0);
        atomicAdd(&s_sum[col + 1], s1);
        atomicAdd(&s_sq[col + 1], q1);
    }
    __syncthreads();
    if (tid < F) {
        atomicAdd(&stats[tid], s_sum[tid]);
        atomicAdd(&stats[F + tid], s_sq[tid]);
    }
}

// - classifier: fused BN(from raw stats)+ReLU + GEMM + log_softmax (fp16 H in) -
__global__ __launch_bounds__(256) void classifier_kernel(const uint2* __restrict__ H,
                                                         const float* __restrict__ Wc,
                                                         const float* __restrict__ bc,
                                                         const float* __restrict__ g,
                                                         const float* __restrict__ be,
                                                         float* __restrict__ outb, int n) {
    __shared__ float sbuf[6656];
    float* As    = sbuf;           // [8][128]  during k-loop
    float* Ws    = sbuf + 1024;    // [128][40]
    float* s_log = sbuf;           // overlay after k-loop: [128][41]
    float* s_lse = sbuf + 5248;    // [128]
    float* s_sc  = sbuf + 6144;    // [128]
    float* s_sh  = sbuf + 6272;    // [128]

    int tid = threadIdx.x;
    int row0 = blockIdx.x * 128;

    if (tid < F) {
        float mean = g_stats[2 * F + tid] / (float)n;
        float var  = g_stats[3 * F + tid] / (float)n - mean * mean;
        float sck = g[tid] * rsqrtf(var + BN_EPS);
        s_sc[tid] = sck;
        s_sh[tid] = be[tid] - mean * sck;
    }
    for (int idx = tid; idx < F * NCLSK; idx += 256) Ws[idx] = Wc[idx];

    int tx = tid & 7;
    int ty = tid >> 3;

    float acc[4][5];
    #pragma unroll
    for (int i = 0; i < 4; i++)
        #pragma unroll
        for (int j = 0; j < 5; j++) acc[i][j] = 0.f;

    int lrow = tid >> 1;
    int seg  = (tid & 1) * 4;
    int segu = tid & 1;
    int grow = row0 + lrow;
    bool rok = grow < n;
    const uint2* hp = H + (size_t)grow * 32;
    __syncthreads();

    for (int k0 = 0; k0 < F; k0 += 8) {
        uint2 hv = make_uint2(0u, 0u);
        if (rok) hv = __ldg(&hp[k0 / 4 + segu]);
        float2 f01 = __half22float2(*(__half2*)&hv.x);
        float2 f23 = __half22float2(*(__half2*)&hv.y);
        float4 sc = *(const float4*)&s_sc[k0 + seg];
        float4 sh = *(const float4*)&s_sh[k0 + seg];
        float vx = fmaxf(f01.x * sc.x + sh.x, 0.f);
        float vy = fmaxf(f01.y * sc.y + sh.y, 0.f);
        float vz = fmaxf(f23.x * sc.z + sh.z, 0.f);
        float vw = fmaxf(f23.y * sc.w + sh.w, 0.f);
        As[(seg + 0) * 128 + lrow] = vx;
        As[(seg + 1) * 128 + lrow] = vy;
        As[(seg + 2) * 128 + lrow] = vz;
        As[(seg + 3) * 128 + lrow] = vw;
        __syncthreads();
        #pragma unroll
        for (int kk = 0; kk < 8; kk++) {
            float ra[4], rb[5];
            #pragma unroll
            for (int i = 0; i < 4; i++) ra[i] = As[kk * 128 + ty * 4 + i];
            #pragma unroll
            for (int j = 0; j < 5; j++) rb[j] = Ws[(k0 + kk) * NCLSK + tx * 5 + j];
            #pragma unroll
            for (int i = 0; i < 4; i++)
                #pragma unroll
                for (int j = 0; j < 5; j++) acc[i][j] += ra[i] * rb[j];
        }
        __syncthreads();
    }

    float bias_r[5];
    #pragma unroll
    for (int j = 0; j < 5; j++) bias_r[j] = __ldg(&bc[tx * 5 + j]);

    #pragma unroll
    for (int i = 0; i < 4; i++)
        #pragma unroll
        for (int j = 0; j < 5; j++)
            s_log[(ty * 4 + i) * 41 + tx * 5 + j] = acc[i][j] + bias_r[j];
    __syncthreads();

    if (tid < 128) {
        float m = -INFINITY;
        #pragma unroll
        for (int c = 0; c < NCLSK; c++) m = fmaxf(m, s_log[tid * 41 + c]);
        float s = 0.f;
        #pragma unroll
        for (int c = 0; c < NCLSK; c++) s += __expf(s_log[tid * 41 + c] - m);
        s_lse[tid] = m + __logf(s);
    }
    __syncthreads();

    int rows = n - row0;
    if (rows > 128) rows = 128;
    int total = rows * NCLSK;
    for (int idx = tid; idx < total; idx += 256) {
        int r = idx / NCLSK;
        int c = idx - r * NCLSK;
        outb[(size_t)(row0 + r) * NCLSK + c] = s_log[r * 41 + c] - s_lse[r];
    }
}

// ---------------- launch ----------------
extern "C" void kernel_launch(void* const* d_in, const int* in_sizes, int n_in,
                              void* d_out, int out_size) {
    const float* x  = (const float*)d_in[0];
    const int*   ei = (const int*)d_in[1];     // int32 (JAX x64 disabled)
    const float* W0 = (const float*)d_in[2];
    const float* b0 = (const float*)d_in[3];
    const float* g0 = (const float*)d_in[4];
    const float* be0 = (const float*)d_in[5];
    const float* W1 = (const float*)d_in[6];
    const float* b1 = (const float*)d_in[7];
    const float* g1 = (const float*)d_in[8];
    const float* be1 = (const float*)d_in[9];
    const float* Wc = (const float*)d_in[10];
    const float* bc = (const float*)d_in[11];
    float* out = (float*)d_out;

    int n  = in_sizes[0] / F;
    int ne = in_sizes[1] / 2;

    void *p_agg, *p_h0, *p_h1, *p_deg, *p_stats, *p_wt0, *p_wt1;
    cudaGetSymbolAddress(&p_agg, g_aggh);
    cudaGetSymbolAddress(&p_h0, g_hlin0);
    cudaGetSymbolAddress(&p_h1, g_hlin1);
    cudaGetSymbolAddress(&p_deg, g_deg);
    cudaGetSymbolAddress(&p_stats, g_stats);
    cudaGetSymbolAddress(&p_wt0, g_wt0);
    cudaGetSymbolAddress(&p_wt1, g_wt1);
    uint2*  aggh   = (uint2*)p_agg;
    uint2*  h0     = (uint2*)p_h0;
    uint2*  h1     = (uint2*)p_h1;
    float*  stats0 = (float*)p_stats;
    float*  stats1 = stats0 + 2 * F;
    uint4*  wt0    = (uint4*)p_wt0;
    uint4*  wt1    = (uint4*)p_wt1;

    cudaFuncSetAttribute(gemm_hmma_stats_kernel,
                         cudaFuncAttributeMaxDynamicSharedMemorySize,
                         GEMM_SMEM_BYTES);

    int total4 = n * (F / 4);   // uint2 units per feature matrix
    int ne4 = (ne + 3) / 4;
    int convB = (total4 + 255) / 256;
    int histB = (ne4 + 255) / 256;

    // CSR build + conversions
    cudaMemsetAsync(p_deg, 0, (size_t)n * sizeof(int));
    conv_hist_kernel<<<convB + histB, 256>>>((const float4*)x, total4, ei, ne, n, convB);
    wconv_kernel<<<(2 * F * 136 + 255) / 256, 256>>>(W0, W1);
    scan_blocks_kernel<<<(n + 255) / 256, 256>>>(n);
    fill_kernel<<<(ne4 + 255) / 256, 256>>>(ei, ne, n);

    int agg_blocks  = (n + 7) / 8;
    int gemm_blocks = (n + 127) / 128;

    // ---- layer 0 ----
    agg_h_kernel<<<agg_blocks, 256>>>(aggh, n);
    gemm_hmma_stats_kernel<<<gemm_blocks, 256, GEMM_SMEM_BYTES>>>(
        (const uint4*)aggh, wt0, b0, (uint32*)h0, stats0, n);

    // ---- layer 1: node-wise BN0+ReLU -> fp16, then gather ----
    bnrelu_h_kernel<<<(total4 + 255) / 256, 256>>>(h0, stats0, g0, be0, n, total4);
    agg_h_kernel<<<agg_blocks, 256>>>(aggh, n);
    gemm_hmma_stats_kernel<<<gemm_blocks, 256, GEMM_SMEM_BYTES>>>(
        (const uint4*)aggh, wt1, b1, (uint32*)h1, stats1, n);

    // ---- classifier: fused BN1+ReLU + GEMM + log_softmax ----
    classifier_kernel<<<gemm_blocks, 256>>>(h1, Wc, bc, g1, be1, out, n);
}

// round 16
// speedup vs baseline: 1.0544x; 1.0544x over previous
#include <cuda_runtime.h>
#include <cuda_fp16.h>
#include <math.h>

#define NMAX 50000
#define EMAX 600000
#define F    128
#define NCLSK 40
#define BN_EPS 1e-5f

typedef unsigned long long u64;
typedef unsigned int uint32;

__device__ __forceinline__ u64 pack_dup(float a) {
    u64 r;
    asm("mov.b64 %0, {%1, %1};" : "=l"(r) : "f"(a));
    return r;
}
__device__ __forceinline__ void ffma2(u64 &d, u64 a, u64 b) {
    asm("fma.rn.f32x2 %0, %1, %2, %0;" : "+l"(d) : "l"(a), "l"(b));
}
__device__ __forceinline__ float2 unpack2(u64 v) {
    float lo, hi;
    asm("mov.b64 {%0, %1}, %2;" : "=f"(lo), "=f"(hi) : "l"(v));
    return make_float2(lo, hi);
}

// ---------------- scratch (device globals; no allocation allowed) ----------------
__device__ uint2  g_aggh  [NMAX * 32];  // fp16 aggregation output (GEMM A input)
__device__ uint2  g_hlin0 [NMAX * 32];  // layer-0 GEMM output (fp16, pre-BN)
__device__ uint2  g_hlin1 [NMAX * 32];  // layer-1 GEMM output (fp16, pre-BN)
__device__ uint2  g_feath [NMAX * 32];  // fp16 feature rows (gather source)
__device__ int    g_deg [NMAX];
__device__ int    g_off [NMAX];
__device__ int    g_cur [NMAX];
__device__ int    g_csrc[EMAX];         // stores src*32 (uint2 row base index)
__device__ float  g_invdeg[NMAX];
__device__ float  g_stats[4 * F];   // layer0: [0..255], layer1: [256..511]
__device__ int    g_counter;

// ------ combined: fp32->fp16 convert of x  +  degree histogram (1 edge/thr) ------
__global__ __launch_bounds__(256) void conv_hist_kernel(const float4* __restrict__ x,
                                                        int total4,
                                                        const int* __restrict__ ei,
                                                        int ne, int n, int convB) {
    int tid = threadIdx.x;
    if (blockIdx.x == 0) {
        g_stats[tid] = 0.f;
        g_stats[256 + tid] = 0.f;
        if (tid == 0) g_counter = 0;
    }
    if (blockIdx.x < convB) {
        int i = blockIdx.x * 256 + tid;
        if (i < total4) {
            float4 v = __ldg(&x[i]);
            __half2 h01 = __floats2half2_rn(v.x, v.y);
            __half2 h23 = __floats2half2_rn(v.z, v.w);
            uint2 r;
            r.x = *(uint32*)&h01;
            r.y = *(uint32*)&h23;
            g_feath[i] = r;
        }
    } else {
        int e = (blockIdx.x - convB) * 256 + tid;
        if (e < ne) {
            int d = __ldg(&ei[ne + e]);
            if ((unsigned)d < (unsigned)n) atomicAdd(&g_deg[d], 1);
        }
    }
}

// -- node-wise BN+ReLU on fp16 h -> fp16 features for the next gather --------
__global__ __launch_bounds__(256) void bnrelu_h_kernel(const uint2* __restrict__ h,
                                                       const float* __restrict__ stats,
                                                       const float* __restrict__ g,
                                                       const float* __restrict__ be,
                                                       int n, int total4) {
    __shared__ float s_sc[F], s_sh[F];
    int tid = threadIdx.x;
    if (tid < F) {
        float mean = stats[tid] / (float)n;
        float var  = stats[F + tid] / (float)n - mean * mean;
        float sck = g[tid] * rsqrtf(var + BN_EPS);
        s_sc[tid] = sck;
        s_sh[tid] = be[tid] - mean * sck;
    }
    __syncthreads();
    int i = blockIdx.x * 256 + tid;
    if (i < total4) {
        int c4 = (i & 31) * 4;
        uint2 hv = __ldg(&h[i]);
        float2 f01 = __half22float2(*(__half2*)&hv.x);
        float2 f23 = __half22float2(*(__half2*)&hv.y);
        float4 sc = *(const float4*)&s_sc[c4];
        float4 sh = *(const float4*)&s_sh[c4];
        float vx = fmaxf(f01.x * sc.x + sh.x, 0.f);
        float vy = fmaxf(f01.y * sc.y + sh.y, 0.f);
        float vz = fmaxf(f23.x * sc.z + sh.z, 0.f);
        float vw = fmaxf(f23.y * sc.w + sh.w, 0.f);
        __half2 h01 = __floats2half2_rn(vx, vy);
        __half2 h23 = __floats2half2_rn(vz, vw);
        uint2 r;
        r.x = *(uint32*)&h01;
        r.y = *(uint32*)&h23;
        g_feath[i] = r;
    }
}

// ---------------- one-pass block scan with atomic base ----------------
__global__ __launch_bounds__(256) void scan_blocks_kernel(int n) {
    int tid = threadIdx.x;
    int i = blockIdx.x * 256 + tid;
    int v = (i < n) ? g_deg[i] : 0;

    int incl = v;
    #pragma unroll
    for (int o = 1; o < 32; o <<= 1) {
        int t = __shfl_up_sync(0xffffffffu, incl, o);
        if ((tid & 31) >= o) incl += t;
    }
    __shared__ int wsum[8];
    if ((tid & 31) == 31) wsum[tid >> 5] = incl;
    __syncthreads();
    if (tid < 8) {
        int w = wsum[tid];
        int s = w;
        #pragma unroll
        for (int o = 1; o < 8; o <<= 1) {
            int t = __shfl_up_sync(0x000000ffu, s, o);
            if (tid >= o) s += t;
        }
        wsum[tid] = s - w;
    }
    __syncthreads();
    incl += wsum[tid >> 5];

    __shared__ int base_s;
    if (tid == 255) base_s = atomicAdd(&g_counter, incl);
    __syncthreads();

    if (i < n) {
        int off = base_s + incl - v;
        g_off[i] = off;
        g_cur[i] = off;
        g_invdeg[i] = 1.0f / fmaxf((float)v, 1.0f);
    }
}

// ------ CSR fill, 1 edge/thread (R9-proven); stores src*32 ------
__global__ __launch_bounds__(256) void fill_kernel(const int* __restrict__ ei,
                                                   int ne, int n) {
    int e = blockIdx.x * 256 + threadIdx.x;
    if (e < ne) {
        int d = __ldg(&ei[ne + e]);
        int s = __ldg(&ei[e]);
        if ((unsigned)d < (unsigned)n && (unsigned)s < (unsigned)n) {
            int p = atomicAdd(&g_cur[d], 1);
            g_csrc[p] = s * 32;
        }
    }
}

// -- mean aggregation over fp16 rows, pairwise HADD2; emits fp16 (uint2/lane) --
__global__ __launch_bounds__(256, 6) void agg_h_kernel(uint2* __restrict__ outh, int n) {
    int wid  = threadIdx.x >> 5;
    int lane = threadIdx.x & 31;
    int node = blockIdx.x * 8 + wid;
    if (node >= n) return;
    int beg = g_off[node];
    int deg = g_deg[node];
    int end = beg + deg;
    float4 acc = make_float4(0.f, 0.f, 0.f, 0.f);
    int e = beg;
    int m4 = beg + (deg & ~3);
    for (; e < m4; e += 4) {
        int i0 = g_csrc[e],   i1 = g_csrc[e+1];
        int i2 = g_csrc[e+2], i3 = g_csrc[e+3];
        uint2 r0 = __ldg(&g_feath[i0 + lane]);
        uint2 r1 = __ldg(&g_feath[i1 + lane]);
        uint2 r2 = __ldg(&g_feath[i2 + lane]);
        uint2 r3 = __ldg(&g_feath[i3 + lane]);
        __half2 s0x = __hadd2(*(__half2*)&r0.x, *(__half2*)&r1.x);
        __half2 s0y = __hadd2(*(__half2*)&r0.y, *(__half2*)&r1.y);
        __half2 s1x = __hadd2(*(__half2*)&r2.x, *(__half2*)&r3.x);
        __half2 s1y = __hadd2(*(__half2*)&r2.y, *(__half2*)&r3.y);
        float2 f0x = __half22float2(s0x);
        float2 f0y = __half22float2(s0y);
        float2 f1x = __half22float2(s1x);
        float2 f1y = __half22float2(s1y);
        acc.x += f0x.x + f1x.x;
        acc.y += f0x.y + f1x.y;
        acc.z += f0y.x + f1y.x;
        acc.w += f0y.y + f1y.y;
    }
    if (e + 1 < end) {
        int i0 = g_csrc[e], i1 = g_csrc[e+1];
        uint2 r0 = __ldg(&g_feath[i0 + lane]);
        uint2 r1 = __ldg(&g_feath[i1 + lane]);
        __half2 sx = __hadd2(*(__half2*)&r0.x, *(__half2*)&r1.x);
        __half2 sy = __hadd2(*(__half2*)&r0.y, *(__half2*)&r1.y);
        float2 fx = __half22float2(sx);
        float2 fy = __half22float2(sy);
        acc.x += fx.x; acc.y += fx.y; acc.z += fy.x; acc.w += fy.y;
        e += 2;
    }
    if (e < end) {
        int i0 = g_csrc[e];
        uint2 r0 = __ldg(&g_feath[i0 + lane]);
        float2 p0 = __half22float2(*(__half2*)&r0.x);
        float2 p1 = __half22float2(*(__half2*)&r0.y);
        acc.x += p0.x; acc.y += p0.y; acc.z += p1.x; acc.w += p1.y;
    }
    float inv = g_invdeg[node];
    __half2 o01 = __floats2half2_rn(acc.x * inv, acc.y * inv);
    __half2 o23 = __floats2half2_rn(acc.z * inv, acc.w * inv);
    uint2 o;
    o.x = *(uint32*)&o01;
    o.y = *(uint32*)&o23;
    outh[node * 32 + lane] = o;
}

// -- SGEMM (FFMA2, double-buffered): fp16 A in, fp16 C out, fp32 math+stats --
#define GBM 128
#define GBK 8
__global__ __launch_bounds__(256) void gemm_stats_kernel(const uint2* __restrict__ Ah,
                                                         const float* __restrict__ W,
                                                         const float* __restrict__ bias,
                                                         uint2* __restrict__ C,
                                                         float* __restrict__ stats, int n) {
    __shared__ float As[2][GBK][GBM];
    __shared__ float Bs[2][GBK][F];
    __shared__ float s_sum[F];
    __shared__ float s_sq[F];

    int block_row = blockIdx.x * GBM;
    int tid = threadIdx.x;
    int tx = tid & 15, ty = tid >> 4;

    int a_row = tid >> 1;
    int a_k   = (tid & 1) * 4;      // float offset within k-chunk
    int a_u   = tid & 1;            // uint2 offset within k-chunk
    int b_k   = tid >> 5;
    int b_col = (tid & 31) * 4;

    int grow = block_row + a_row;
    bool arow_ok = grow < n;
    const uint2* aptr = Ah + (size_t)grow * 32;

    u64 acc2[8][4];
    #pragma unroll
    for (int i = 0; i < 8; i++)
        #pragma unroll
        for (int j = 0; j < 4; j++) acc2[i][j] = 0ULL;

    // prologue: tile 0
    uint2 hz = make_uint2(0u, 0u);
    uint2 hv = arow_ok ? __ldg(&aptr[a_u]) : hz;
    {
        float2 f01 = __half22float2(*(__half2*)&hv.x);
        float2 f23 = __half22float2(*(__half2*)&hv.y);
        As[0][a_k + 0][a_row] = f01.x;
        As[0][a_k + 1][a_row] = f01.y;
        As[0][a_k + 2][a_row] = f23.x;
        As[0][a_k + 3][a_row] = f23.y;
    }
    float4 bv = *(const float4*)(W + (size_t)b_k * F + b_col);
    *(float4*)&Bs[0][b_k][b_col] = bv;
    __syncthreads();

    int buf = 0;
    #pragma unroll
    for (int k0 = 0; k0 < F; k0 += GBK) {
        uint2 nhv;
        float4 nbv;
        bool more = (k0 + GBK) < F;
        if (more) {
            nhv = arow_ok ? __ldg(&aptr[(k0 + GBK) / 4 + a_u]) : hz;
            nbv = *(const float4*)(W + (size_t)(k0 + GBK + b_k) * F + b_col);
        }
        #pragma unroll
        for (int kk = 0; kk < GBK; kk++) {
            float4 a0 = *(const float4*)&As[buf][kk][ty * 8];
            float4 a1 = *(const float4*)&As[buf][kk][ty * 8 + 4];
            ulonglong2 b01 = *(const ulonglong2*)&Bs[buf][kk][tx * 8];
            ulonglong2 b23 = *(const ulonglong2*)&Bs[buf][kk][tx * 8 + 4];
            u64 rb[4] = {b01.x, b01.y, b23.x, b23.y};
            u64 ra[8] = {pack_dup(a0.x), pack_dup(a0.y), pack_dup(a0.z), pack_dup(a0.w),
                         pack_dup(a1.x), pack_dup(a1.y), pack_dup(a1.z), pack_dup(a1.w)};
            #pragma unroll
            for (int i = 0; i < 8; i++)
                #pragma unroll
                for (int j = 0; j < 4; j++) ffma2(acc2[i][j], ra[i], rb[j]);
        }
        if (more) {
            int nb = buf ^ 1;
            float2 f01 = __half22float2(*(__half2*)&nhv.x);
            float2 f23 = __half22float2(*(__half2*)&nhv.y);
            As[nb][a_k + 0][a_row] = f01.x;
            As[nb][a_k + 1][a_row] = f01.y;
            As[nb][a_k + 2][a_row] = f23.x;
            As[nb][a_k + 3][a_row] = f23.y;
            *(float4*)&Bs[nb][b_k][b_col] = nbv;
        }
        __syncthreads();
        buf ^= 1;
    }

    float bias_r[8];
    #pragma unroll
    for (int j = 0; j < 8; j++) bias_r[j] = __ldg(&bias[tx * 8 + j]);

    if (tid < F) { s_sum[tid] = 0.f; s_sq[tid] = 0.f; }
    __syncthreads();

    float ps[8], pq[8];
    #pragma unroll
    for (int j = 0; j < 8; j++) { ps[j] = 0.f; pq[j] = 0.f; }

    #pragma unroll
    for (int i = 0; i < 8; i++) {
        int r = block_row + ty * 8 + i;
        if (r < n) {
            float va[8];
            #pragma unroll
            for (int jp = 0; jp < 4; jp++) {
                float2 p = unpack2(acc2[i][jp]);
                va[jp * 2 + 0] = p.x + bias_r[jp * 2 + 0];
                va[jp * 2 + 1] = p.y + bias_r[jp * 2 + 1];
            }
            __half2 hA = __floats2half2_rn(va[0], va[1]);
            __half2 hB = __floats2half2_rn(va[2], va[3]);
            __half2 hC = __floats2half2_rn(va[4], va[5]);
            __half2 hD = __floats2half2_rn(va[6], va[7]);
            uint2 o0, o1;
            o0.x = *(uint32*)&hA; o0.y = *(uint32*)&hB;
            o1.x = *(uint32*)&hC; o1.y = *(uint32*)&hD;
            C[(size_t)r * 32 + tx * 2 + 0] = o0;
            C[(size_t)r * 32 + tx * 2 + 1] = o1;
            #pragma unroll
            for (int j = 0; j < 8; j++) { ps[j] += va[j]; pq[j] += va[j] * va[j]; }
        }
    }
    #pragma unroll
    for (int j = 0; j < 8; j++) {
        atomicAdd(&s_sum[tx * 8 + j], ps[j]);
        atomicAdd(&s_sq[tx * 8 + j], pq[j]);
    }
    __syncthreads();
    if (tid < F) {
        atomicAdd(&stats[tid], s_sum[tid]);
        atomicAdd(&stats[F + tid], s_sq[tid]);
    }
}

// - classifier: fused BN(from raw stats)+ReLU + GEMM + log_softmax (fp16 H in) -
__global__ __launch_bounds__(256) void classifier_kernel(const uint2* __restrict__ H,
                                                         const float* __restrict__ Wc,
                                                         const float* __restrict__ bc,
                                                         const float* __restrict__ g,
                                                         const float* __restrict__ be,
                                                         float* __restrict__ outb, int n) {
    __shared__ float sbuf[6656];
    float* As    = sbuf;           // [8][128]  during k-loop
    float* Ws    = sbuf + 1024;    // [128][40]
    float* s_log = sbuf;           // overlay after k-loop: [128][41]
    float* s_lse = sbuf + 5248;    // [128]
    float* s_sc  = sbuf + 6144;    // [128]
    float* s_sh  = sbuf + 6272;    // [128]

    int tid = threadIdx.x;
    int row0 = blockIdx.x * 128;

    if (tid < F) {
        float mean = g_stats[2 * F + tid] / (float)n;
        float var  = g_stats[3 * F + tid] / (float)n - mean * mean;
        float sck = g[tid] * rsqrtf(var + BN_EPS);
        s_sc[tid] = sck;
        s_sh[tid] = be[tid] - mean * sck;
    }
    for (int idx = tid; idx < F * NCLSK; idx += 256) Ws[idx] = Wc[idx];

    int tx = tid & 7;
    int ty = tid >> 3;

    float acc[4][5];
    #pragma unroll
    for (int i = 0; i < 4; i++)
        #pragma unroll
        for (int j = 0; j < 5; j++) acc[i][j] = 0.f;

    int lrow = tid >> 1;
    int seg  = (tid & 1) * 4;
    int segu = tid & 1;
    int grow = row0 + lrow;
    bool rok = grow < n;
    const uint2* hp = H + (size_t)grow * 32;
    __syncthreads();

    for (int k0 = 0; k0 < F; k0 += 8) {
        uint2 hv = make_uint2(0u, 0u);
        if (rok) hv = __ldg(&hp[k0 / 4 + segu]);
        float2 f01 = __half22float2(*(__half2*)&hv.x);
        float2 f23 = __half22float2(*(__half2*)&hv.y);
        float4 sc = *(const float4*)&s_sc[k0 + seg];
        float4 sh = *(const float4*)&s_sh[k0 + seg];
        float vx = fmaxf(f01.x * sc.x + sh.x, 0.f);
        float vy = fmaxf(f01.y * sc.y + sh.y, 0.f);
        float vz = fmaxf(f23.x * sc.z + sh.z, 0.f);
        float vw = fmaxf(f23.y * sc.w + sh.w, 0.f);
        As[(seg + 0) * 128 + lrow] = vx;
        As[(seg + 1) * 128 + lrow] = vy;
        As[(seg + 2) * 128 + lrow] = vz;
        As[(seg + 3) * 128 + lrow] = vw;
        __syncthreads();
        #pragma unroll
        for (int kk = 0; kk < 8; kk++) {
            float ra[4], rb[5];
            #pragma unroll
            for (int i = 0; i < 4; i++) ra[i] = As[kk * 128 + ty * 4 + i];
            #pragma unroll
            for (int j = 0; j < 5; j++) rb[j] = Ws[(k0 + kk) * NCLSK + tx * 5 + j];
            #pragma unroll
            for (int i = 0; i < 4; i++)
                #pragma unroll
                for (int j = 0; j < 5; j++) acc[i][j] += ra[i] * rb[j];
        }
        __syncthreads();
    }

    float bias_r[5];
    #pragma unroll
    for (int j = 0; j < 5; j++) bias_r[j] = __ldg(&bc[tx * 5 + j]);

    #pragma unroll
    for (int i = 0; i < 4; i++)
        #pragma unroll
        for (int j = 0; j < 5; j++)
            s_log[(ty * 4 + i) * 41 + tx * 5 + j] = acc[i][j] + bias_r[j];
    __syncthreads();

    if (tid < 128) {
        float m = -INFINITY;
        #pragma unroll
        for (int c = 0; c < NCLSK; c++) m = fmaxf(m, s_log[tid * 41 + c]);
        float s = 0.f;
        #pragma unroll
        for (int c = 0; c < NCLSK; c++) s += __expf(s_log[tid * 41 + c] - m);
        s_lse[tid] = m + __logf(s);
    }
    __syncthreads();

    int rows = n - row0;
    if (rows > 128) rows = 128;
    int total = rows * NCLSK;
    for (int idx = tid; idx < total; idx += 256) {
        int r = idx / NCLSK;
        int c = idx - r * NCLSK;
        outb[(size_t)(row0 + r) * NCLSK + c] = s_log[r * 41 + c] - s_lse[r];
    }
}

// ---------------- launch ----------------
extern "C" void kernel_launch(void* const* d_in, const int* in_sizes, int n_in,
                              void* d_out, int out_size) {
    const float* x  = (const float*)d_in[0];
    const int*   ei = (const int*)d_in[1];     // int32 (JAX x64 disabled)
    const float* W0 = (const float*)d_in[2];
    const float* b0 = (const float*)d_in[3];
    const float* g0 = (const float*)d_in[4];
    const float* be0 = (const float*)d_in[5];
    const float* W1 = (const float*)d_in[6];
    const float* b1 = (const float*)d_in[7];
    const float* g1 = (const float*)d_in[8];
    const float* be1 = (const float*)d_in[9];
    const float* Wc = (const float*)d_in[10];
    const float* bc = (const float*)d_in[11];
    float* out = (float*)d_out;

    int n  = in_sizes[0] / F;
    int ne = in_sizes[1] / 2;

    void *p_agg, *p_h0, *p_h1, *p_deg, *p_stats;
    cudaGetSymbolAddress(&p_agg, g_aggh);
    cudaGetSymbolAddress(&p_h0, g_hlin0);
    cudaGetSymbolAddress(&p_h1, g_hlin1);
    cudaGetSymbolAddress(&p_deg, g_deg);
    cudaGetSymbolAddress(&p_stats, g_stats);
    uint2* aggh   = (uint2*)p_agg;
    uint2* h0     = (uint2*)p_h0;
    uint2* h1     = (uint2*)p_h1;
    float* stats0 = (float*)p_stats;
    float* stats1 = stats0 + 2 * F;

    int total4 = n * (F / 4);   // uint2 units per feature matrix
    int convB = (total4 + 255) / 256;
    int histB = (ne + 255) / 256;

    // CSR build + fp16 conversion of x (conversion fused into hist launch)
    cudaMemsetAsync(p_deg, 0, (size_t)n * sizeof(int));
    conv_hist_kernel<<<convB + histB, 256>>>((const float4*)x, total4, ei, ne, n, convB);
    scan_blocks_kernel<<<(n + 255) / 256, 256>>>(n);
    fill_kernel<<<(ne + 255) / 256, 256>>>(ei, ne, n);

    int agg_blocks  = (n + 7) / 8;
    int gemm_blocks = (n + GBM - 1) / GBM;

    // ---- layer 0 ----
    agg_h_kernel<<<agg_blocks, 256>>>(aggh, n);
    gemm_stats_kernel<<<gemm_blocks, 256>>>(aggh, W0, b0, h0, stats0, n);

    // ---- layer 1: node-wise BN0+ReLU -> fp16, then gather ----
    bnrelu_h_kernel<<<(total4 + 255) / 256, 256>>>(h0, stats0, g0, be0, n, total4);
    agg_h_kernel<<<agg_blocks, 256>>>(aggh, n);
    gemm_stats_kernel<<<gemm_blocks, 256>>>(aggh, W1, b1, h1, stats1, n);

    // ---- classifier: fused BN1+ReLU + GEMM + log_softmax ----
    classifier_kernel<<<gemm_blocks, 256>>>(h1, Wc, bc, g1, be1, out, n);
}